// round 1
// baseline (speedup 1.0000x reference)
#include <cuda_runtime.h>

// Path signature depth-4, C=10, L=512, B from in_sizes.
// One CTA per batch element. Thread p (0..999) owns level-3 entry p and
// level-4 entries [p*10 .. p*10+9] in registers. Levels 1,2 live in
// double-buffered shared memory. Each Chen step is one FMA per level-4
// element because exp(dx) levels are rank-1 in dx.

#define SIG_C 10
#define SIG_L 512
#define SIG_NSTEP 511   // number of increments
#define SIG_NP 1000     // level-3 size = C^3
#define SIG_OUT 11110   // 10 + 100 + 1000 + 10000

__global__ __launch_bounds__(1024, 1)
void sig_depth4_kernel(const float* __restrict__ path, float* __restrict__ out) {
    // increments padded to 12 floats per step => 48B stride, 16B-aligned float4 loads
    __shared__ float dxs[SIG_NSTEP * 12];
    __shared__ float l1s[2][16];
    __shared__ float l2s[2][112];

    const int b   = blockIdx.x;
    const int tid = threadIdx.x;
    const float* prow = path + (size_t)b * SIG_L * SIG_C;

    // Precompute all increments into shared memory.
    for (int i = tid; i < SIG_NSTEP * SIG_C; i += blockDim.x) {
        int t = i / SIG_C;
        int c = i - t * SIG_C;
        dxs[t * 12 + c] = prow[(t + 1) * SIG_C + c] - prow[t * SIG_C + c];
    }
    __syncthreads();

    const int  p      = tid;
    const bool active = (p < SIG_NP);
    const int  i1 = p / 100;
    const int  i2 = (p / 10) % 10;
    const int  i3 = p % 10;

    float dx[10];
    // load dx_0 (broadcast LDS.128 x3; last 2 lanes of pad are unused garbage)
    {
        const float4* v = reinterpret_cast<const float4*>(dxs);
        float4 a = v[0], bq = v[1], cq = v[2];
        dx[0]=a.x; dx[1]=a.y; dx[2]=a.z; dx[3]=a.w;
        dx[4]=bq.x; dx[5]=bq.y; dx[6]=bq.z; dx[7]=bq.w;
        dx[8]=cq.x; dx[9]=cq.y;
    }

    // ---- init: signature of first segment = exp(dx_0) ----
    float l3 = 0.0f;
    float l4[10];
#pragma unroll
    for (int q = 0; q < 10; ++q) l4[q] = 0.0f;

    if (active) {
        float e3p = dx[i1] * dx[i2] * dx[i3] * (1.0f / 6.0f);
        l3 = e3p;
        float c4 = e3p * 0.25f;  // /24 total
#pragma unroll
        for (int q = 0; q < 10; ++q) l4[q] = c4 * dx[q];
    }
    if (p < 100) l2s[0][p] = dx[p / 10] * dx[p % 10] * 0.5f;
    if (p < 10)  l1s[0][p] = dx[p];
    __syncthreads();

    // ---- Chen scan over remaining 510 increments ----
    int cur = 0;
    for (int t = 1; t < SIG_NSTEP; ++t) {
        const float4* v = reinterpret_cast<const float4*>(dxs + t * 12);
        float4 a = v[0], bq = v[1], cq = v[2];
        dx[0]=a.x; dx[1]=a.y; dx[2]=a.z; dx[3]=a.w;
        dx[4]=bq.x; dx[5]=bq.y; dx[6]=bq.z; dx[7]=bq.w;
        dx[8]=cq.x; dx[9]=cq.y;

        const int nxt = cur ^ 1;

        if (active) {
            float l2v = l2s[cur][i1 * 10 + i2];
            float l1v = l1s[cur][i1];
            float d23 = dx[i2] * dx[i3];
            float e3p = dx[i1] * d23 * (1.0f / 6.0f);
            // level-4: new4[p,q] = l4[p,q] + coef * dx[q]
            float coef = l3 + 0.25f * e3p
                       + 0.5f * l2v * dx[i3]
                       + (1.0f / 6.0f) * l1v * d23;
#pragma unroll
            for (int q = 0; q < 10; ++q) l4[q] = fmaf(coef, dx[q], l4[q]);
            // level-3 update (uses OLD l2, l1 -- read above)
            l3 = l3 + e3p + l2v * dx[i3] + 0.5f * l1v * d23;
        }
        if (p < 100) {
            int j1 = p / 10, j2 = p % 10;
            l2s[nxt][p] = l2s[cur][p] + 0.5f * dx[j1] * dx[j2]
                        + l1s[cur][j1] * dx[j2];
        }
        if (p < 10) l1s[nxt][p] = l1s[cur][p] + dx[p];

        __syncthreads();  // publish nxt buffer for next iteration's reads
        cur = nxt;
    }

    // ---- write out: [l1 | l2 | l3 | l4] per batch ----
    float* ob = out + (size_t)b * SIG_OUT;
    if (p < 10)  ob[p] = l1s[cur][p];
    if (p < 100) ob[10 + p] = l2s[cur][p];
    if (active) {
        ob[110 + p] = l3;
#pragma unroll
        for (int q = 0; q < 10; ++q) ob[1110 + p * 10 + q] = l4[q];
    }
}

extern "C" void kernel_launch(void* const* d_in, const int* in_sizes, int n_in,
                              void* d_out, int out_size) {
    const float* path = (const float*)d_in[0];
    float* out = (float*)d_out;
    int B = in_sizes[0] / (SIG_L * SIG_C);
    sig_depth4_kernel<<<B, 1024>>>(path, out);
}

// round 2
// speedup vs baseline: 5.4250x; 5.4250x over previous
#include <cuda_runtime.h>

// Depth-4 path signature, C=10, L=512.
// Phase 1: split each batch's 511 increments into 2 chunks; one CTA per
//          (batch, chunk) computes the chunk signature with a barrier-free,
//          register-only Chen scan (exp(dx) levels are rank-1 in dx, and
//          thread p only needs the scalars L1[i1], L2[i1,i2], which it tracks
//          privately). Level-4 update uses packed fma.rn.f32x2.
// Phase 2: one CTA per batch merges the two chunk signatures with the full
//          Chen tensor-product identity.

#define SIG_C 10
#define SIG_L 512
#define SIG_NSTEP 511
#define SIG_NP 1000
#define SIG_OUT 11110
#define SIG_S 2
#define SIG_MAXB 128
#define CHUNK0 256

__device__ __align__(16) float g_part[SIG_MAXB * SIG_S * SIG_OUT];

__device__ __forceinline__ unsigned long long ffma2(unsigned long long a,
                                                    unsigned long long b,
                                                    unsigned long long c) {
    unsigned long long d;
    asm("fma.rn.f32x2 %0, %1, %2, %3;" : "=l"(d) : "l"(a), "l"(b), "l"(c));
    return d;
}
__device__ __forceinline__ unsigned long long fmul2(unsigned long long a,
                                                    unsigned long long b) {
    unsigned long long d;
    asm("mul.rn.f32x2 %0, %1, %2;" : "=l"(d) : "l"(a), "l"(b));
    return d;
}
__device__ __forceinline__ unsigned long long pack2(float lo, float hi) {
    unsigned long long d;
    asm("mov.b64 %0, {%1, %2};" : "=l"(d) : "f"(lo), "f"(hi));
    return d;
}

// ---------------- Phase 1: per-chunk signature scan ----------------
__global__ __launch_bounds__(1024, 1)
void sig_scan_kernel(const float* __restrict__ path) {
    // increments padded to 12 floats (48B) per step, 16B aligned
    __shared__ __align__(16) float dxs[CHUNK0 * 12];

    const int b = blockIdx.x >> 1;
    const int c = blockIdx.x & 1;
    const int start = c ? CHUNK0 : 0;
    const int n = c ? (SIG_NSTEP - CHUNK0) : CHUNK0;   // 255 : 256
    const int tid = threadIdx.x;
    const float* prow = path + (size_t)b * SIG_L * SIG_C + (size_t)start * SIG_C;

    for (int i = tid; i < n * SIG_C; i += 1024) {
        int t = i / SIG_C;
        int cc = i - t * SIG_C;
        dxs[t * 12 + cc] = prow[(t + 1) * SIG_C + cc] - prow[t * SIG_C + cc];
    }
    __syncthreads();

    const int p = tid;
    if (p >= SIG_NP) return;
    const int i1 = p / 100;
    const int i2 = (p / 10) % 10;
    const int i3 = p % 10;

    // ---- init with exp(dx_0) ----
    float d1 = dxs[i1], d2 = dxs[i2], d3 = dxs[i3];
    float d23 = d2 * d3;
    float e3p = (d1 * d23) * (1.0f / 6.0f);
    float l1v = d1;
    float l2v = 0.5f * d1 * d2;
    float l3  = e3p;

    unsigned long long l4p[5];
    {
        float c4 = e3p * 0.25f;
        unsigned long long c2 = pack2(c4, c4);
        const ulonglong2* vp = reinterpret_cast<const ulonglong2*>(dxs);
        ulonglong2 va = vp[0];
        ulonglong2 vb = vp[1];
        unsigned long long vc = reinterpret_cast<const unsigned long long*>(dxs)[4];
        l4p[0] = fmul2(c2, va.x);
        l4p[1] = fmul2(c2, va.y);
        l4p[2] = fmul2(c2, vb.x);
        l4p[3] = fmul2(c2, vb.y);
        l4p[4] = fmul2(c2, vc);
    }

    // ---- barrier-free register-only scan ----
    const float* q1 = dxs + i1 + 12;
    const float* q2 = dxs + i2 + 12;
    const float* q3 = dxs + i3 + 12;
    const char*  qv = reinterpret_cast<const char*>(dxs) + 48;

#pragma unroll 4
    for (int t = 1; t < n; ++t) {
        float da = *q1, db = *q2, dc = *q3;
        ulonglong2 va = *reinterpret_cast<const ulonglong2*>(qv);
        ulonglong2 vb = *reinterpret_cast<const ulonglong2*>(qv + 16);
        unsigned long long vc = *reinterpret_cast<const unsigned long long*>(qv + 32);
        q1 += 12; q2 += 12; q3 += 12; qv += 48;

        float d23v = db * dc;
        float u = l2v * dc;                 // old l2
        float v = l1v * d23v;               // old l1
        float e3  = (da * d23v) * (1.0f / 6.0f);
        float coef = fmaf(0.25f, e3, fmaf(0.5f, u, fmaf(1.0f / 6.0f, v, l3)));
        l3 = fmaf(0.5f, v, l3 + e3 + u);
        l2v = fmaf(fmaf(0.5f, da, l1v), db, l2v);   // uses old l1v
        l1v += da;

        unsigned long long c2 = pack2(coef, coef);
        l4p[0] = ffma2(c2, va.x, l4p[0]);
        l4p[1] = ffma2(c2, va.y, l4p[1]);
        l4p[2] = ffma2(c2, vb.x, l4p[2]);
        l4p[3] = ffma2(c2, vb.y, l4p[3]);
        l4p[4] = ffma2(c2, vc,   l4p[4]);
    }

    // ---- write partial signature [l1 |l2 |l3 |l4] ----
    float* dst = g_part + ((size_t)b * SIG_S + c) * SIG_OUT;
    if (i2 == 0 && i3 == 0) dst[i1] = l1v;
    if (i3 == 0) dst[10 + i1 * 10 + i2] = l2v;
    dst[110 + p] = l3;
    unsigned long long* d4 = reinterpret_cast<unsigned long long*>(dst + 1110 + p * 10);
#pragma unroll
    for (int j = 0; j < 5; ++j) d4[j] = l4p[j];
}

// ---------------- Phase 2: Chen combine of 2 chunk signatures ----------------
__global__ __launch_bounds__(1024, 1)
void sig_combine_kernel(float* __restrict__ out) {
    __shared__ float A1[10], A2[100], Bl1[10], Bl2[100], Bl3[1000];
    const int b = blockIdx.x;
    const float* a  = g_part + (size_t)b * SIG_S * SIG_OUT;
    const float* bb = a + SIG_OUT;
    const int tid = threadIdx.x;

    if (tid < 10)  { A1[tid] = a[tid]; Bl1[tid] = bb[tid]; }
    if (tid < 100) { A2[tid] = a[10 + tid]; Bl2[tid] = bb[10 + tid]; }
    if (tid < 1000) Bl3[tid] = bb[110 + tid];
    __syncthreads();

    const int p = tid;
    float* ob = out + (size_t)b * SIG_OUT;

    if (p < 10)  ob[p] = A1[p] + Bl1[p];
    if (p < 100) ob[10 + p] = A2[p] + Bl2[p] + A1[p / 10] * Bl1[p % 10];

    if (p < SIG_NP) {
        const int i1 = p / 100;
        const int i2 = (p / 10) % 10;
        const int i3 = p % 10;
        float a1 = A1[i1];
        float a2 = A2[i1 * 10 + i2];
        float a3 = a[110 + p];

        // level 3: A3 + B3 + A1(x)B2 + A2(x)B1
        ob[110 + p] = a3 + Bl3[p] + a1 * Bl2[i2 * 10 + i3] + a2 * Bl1[i3];

        // level 4: A4 + B4 + A1(x)B3 + A2(x)B2 + A3(x)B1
        const float* A4  = a  + 1110 + p * 10;
        const float* B4  = bb + 1110 + p * 10;
        const float* B3r = Bl3 + i2 * 100 + i3 * 10;
        const float* B2r = Bl2 + i3 * 10;
        float* o4 = ob + 1110 + p * 10;
#pragma unroll
        for (int q = 0; q < 10; ++q) {
            o4[q] = A4[q] + B4[q] + a3 * Bl1[q] + a2 * B2r[q] + a1 * B3r[q];
        }
    }
}

extern "C" void kernel_launch(void* const* d_in, const int* in_sizes, int n_in,
                              void* d_out, int out_size) {
    const float* path = (const float*)d_in[0];
    float* out = (float*)d_out;
    int B = in_sizes[0] / (SIG_L * SIG_C);
    if (B > SIG_MAXB) B = SIG_MAXB;
    sig_scan_kernel<<<B * SIG_S, 1024>>>(path);
    sig_combine_kernel<<<B, 1024>>>(out);
}

// round 4
// speedup vs baseline: 6.8321x; 1.2594x over previous
#include <cuda_runtime.h>

// Depth-4 path signature, C=10, L=512, B=64.
// Phase 1: 2 chunks/batch, one CTA (512 thr) per chunk. Thread t<500 owns
//   rows p=t and p+500 of levels 3/4 (same i2,i3; i1 differs by 5), running
//   BOTH scalar Chen chains packed in f32x2 and 10 packed rank-1 FMAs for
//   level 4. Barrier-free, register-only.
// Phase 2: combine sliced over 10 CTAs per batch (one per i1).

#define SIG_C 10
#define SIG_L 512
#define SIG_NSTEP 511
#define SIG_OUT 11110
#define SIG_MAXB 128
#define CHUNK0 256

typedef unsigned long long u64;

__device__ __align__(16) float g_part[SIG_MAXB * 2 * SIG_OUT];

__device__ __forceinline__ u64 ffma2(u64 a, u64 b, u64 c) {
    u64 d; asm("fma.rn.f32x2 %0, %1, %2, %3;" : "=l"(d) : "l"(a), "l"(b), "l"(c)); return d;
}
__device__ __forceinline__ u64 fmul2(u64 a, u64 b) {
    u64 d; asm("mul.rn.f32x2 %0, %1, %2;" : "=l"(d) : "l"(a), "l"(b)); return d;
}
__device__ __forceinline__ u64 fadd2(u64 a, u64 b) {
    u64 d; asm("add.rn.f32x2 %0, %1, %2;" : "=l"(d) : "l"(a), "l"(b)); return d;
}
__device__ __forceinline__ u64 pack2(float lo, float hi) {
    u64 d; asm("mov.b64 %0, {%1, %2};" : "=l"(d) : "f"(lo), "f"(hi)); return d;
}
__device__ __forceinline__ void unpack2(u64 a, float& lo, float& hi) {
    asm("mov.b64 {%0, %1}, %2;" : "=f"(lo), "=f"(hi) : "l"(a));
}

// ---------------- Phase 1: per-chunk signature scan ----------------
__global__ __launch_bounds__(512, 1)
void sig_scan_kernel(const float* __restrict__ path) {
    __shared__ __align__(16) float dxs[CHUNK0 * 12];

    const int b = blockIdx.x >> 1;
    const int c = blockIdx.x & 1;
    const int start = c ? CHUNK0 : 0;
    const int n = c ? (SIG_NSTEP - CHUNK0) : CHUNK0;   // 255 : 256
    const int tid = threadIdx.x;
    const float* prow = path + (size_t)b * SIG_L * SIG_C + (size_t)start * SIG_C;

    for (int i = tid; i < n * SIG_C; i += 512) {
        int t = i / SIG_C;
        int cc = i - t * SIG_C;
        dxs[t * 12 + cc] = prow[(t + 1) * SIG_C + cc] - prow[t * SIG_C + cc];
    }
    __syncthreads();

    if (tid >= 500) return;
    const int i1 = tid / 100;          // 0..4 ; hi chain uses i1+5
    const int i2 = (tid / 10) % 10;
    const int i3 = tid % 10;

    const u64 c1_2  = pack2(0.5f, 0.5f);
    const u64 c1_6  = pack2(1.0f / 6.0f, 1.0f / 6.0f);
    const u64 c1_24 = pack2(1.0f / 24.0f, 1.0f / 24.0f);

    // ---- init with exp(dx_0) ----
    u64 l1v2, l2v2, l3_2;
    u64 l4lo[5], l4hi[5];
    {
        float Bv = dxs[i2], Cv = dxs[i3];
        u64 A2 = pack2(dxs[i1], dxs[i1 + 5]);
        float d23 = Bv * Cv;
        u64 d23_2 = pack2(d23, d23);
        u64 B2 = pack2(Bv, Bv);
        l1v2 = A2;
        l2v2 = fmul2(fmul2(A2, B2), c1_2);
        l3_2 = fmul2(fmul2(A2, d23_2), c1_6);
        u64 c4 = fmul2(l3_2, pack2(0.25f, 0.25f));
        float clo, chi; unpack2(c4, clo, chi);
        u64 clo2 = pack2(clo, clo), chi2 = pack2(chi, chi);
        ulonglong2 va = *reinterpret_cast<const ulonglong2*>(dxs);
        ulonglong2 vb = *reinterpret_cast<const ulonglong2*>(dxs + 4);
        u64 vc = *reinterpret_cast<const u64*>(dxs + 8);
        l4lo[0] = fmul2(clo2, va.x); l4hi[0] = fmul2(chi2, va.x);
        l4lo[1] = fmul2(clo2, va.y); l4hi[1] = fmul2(chi2, va.y);
        l4lo[2] = fmul2(clo2, vb.x); l4hi[2] = fmul2(chi2, vb.x);
        l4lo[3] = fmul2(clo2, vb.y); l4hi[3] = fmul2(chi2, vb.y);
        l4lo[4] = fmul2(clo2, vc);   l4hi[4] = fmul2(chi2, vc);
    }

    // ---- barrier-free packed scan ----
    const float* base = dxs + 12;
#pragma unroll 4
    for (int t = 1; t < n; ++t) {
        float A_lo = base[i1];
        float A_hi = base[i1 + 5];
        float Bv = base[i2];
        float Cv = base[i3];
        ulonglong2 va = *reinterpret_cast<const ulonglong2*>(base);
        ulonglong2 vb = *reinterpret_cast<const ulonglong2*>(base + 4);
        u64 vc = *reinterpret_cast<const u64*>(base + 8);
        base += 12;

        float d23 = Bv * Cv;
        u64 A2 = pack2(A_lo, A_hi);
        u64 d23_2 = pack2(d23, d23);
        u64 C2 = pack2(Cv, Cv);
        u64 B2 = pack2(Bv, Bv);
        u64 t1 = fmul2(A2, d23_2);           // dx1*dx2*dx3 per chain
        u64 uu = fmul2(l2v2, C2);            // old l2 * dx3
        u64 vv = fmul2(l1v2, d23_2);         // old l1 * dx2*dx3
        u64 coef = ffma2(c1_24, t1, ffma2(c1_2, uu, ffma2(c1_6, vv, l3_2)));
        l3_2 = ffma2(c1_6, t1, ffma2(c1_2, vv, fadd2(l3_2, uu)));
        l2v2 = ffma2(ffma2(c1_2, A2, l1v2), B2, l2v2);  // uses old l1
        l1v2 = fadd2(l1v2, A2);

        float clo, chi; unpack2(coef, clo, chi);
        u64 clo2 = pack2(clo, clo), chi2 = pack2(chi, chi);
        l4lo[0] = ffma2(clo2, va.x, l4lo[0]); l4hi[0] = ffma2(chi2, va.x, l4hi[0]);
        l4lo[1] = ffma2(clo2, va.y, l4lo[1]); l4hi[1] = ffma2(chi2, va.y, l4hi[1]);
        l4lo[2] = ffma2(clo2, vb.x, l4lo[2]); l4hi[2] = ffma2(chi2, vb.x, l4hi[2]);
        l4lo[3] = ffma2(clo2, vb.y, l4lo[3]); l4hi[3] = ffma2(chi2, vb.y, l4hi[3]);
        l4lo[4] = ffma2(clo2, vc,   l4lo[4]); l4hi[4] = ffma2(chi2, vc,   l4hi[4]);
    }

    // ---- write partial signature [l1 | l2 | l3 | l4] ----
    float* dst = g_part + ((size_t)b * 2 + c) * SIG_OUT;
    float lo, hi;
    if (i2 == 0 && i3 == 0) {
        unpack2(l1v2, lo, hi);
        dst[i1] = lo; dst[i1 + 5] = hi;
    }
    if (i3 == 0) {
        unpack2(l2v2, lo, hi);
        dst[10 + i1 * 10 + i2] = lo;
        dst[10 + (i1 + 5) * 10 + i2] = hi;
    }
    unpack2(l3_2, lo, hi);
    dst[110 + tid] = lo;
    dst[110 + tid + 500] = hi;
    u64* d4lo = reinterpret_cast<u64*>(dst + 1110 + (size_t)tid * 10);
    u64* d4hi = reinterpret_cast<u64*>(dst + 1110 + (size_t)(tid + 500) * 10);
#pragma unroll
    for (int j = 0; j < 5; ++j) { d4lo[j] = l4lo[j]; d4hi[j] = l4hi[j]; }
}

// ---------------- Phase 2: Chen combine, 10 CTAs per batch ----------------
__global__ __launch_bounds__(128, 8)
void sig_combine_kernel(float* __restrict__ out) {
    __shared__ float Bl1[10], Bl2[100], Bl3[1000];
    const int b = blockIdx.x / 10;
    const int c = blockIdx.x % 10;        // i1 slice
    const float* a  = g_part + (size_t)b * 2 * SIG_OUT;
    const float* bb = a + SIG_OUT;
    const int tid = threadIdx.x;

    for (int i = tid; i < 1000; i += 128) Bl3[i] = bb[110 + i];
    if (tid < 100) Bl2[tid] = bb[10 + tid];
    if (tid < 10)  Bl1[tid] = bb[tid];
    __syncthreads();

    float* ob = out + (size_t)b * SIG_OUT;

    if (c == 0) {   // this slice also emits levels 1 and 2
        if (tid < 10)  ob[tid] = a[tid] + Bl1[tid];
        if (tid < 100) ob[10 + tid] = a[10 + tid] + Bl2[tid]
                                    + a[tid / 10] * Bl1[tid % 10];
    }

    if (tid < 100) {
        const int i2 = tid / 10;
        const int i3 = tid % 10;
        const int p = c * 100 + tid;
        float a1 = a[c];
        float a2 = a[10 + c * 10 + i2];
        float a3 = a[110 + p];

        // level 3: A3 + B3 + A1(x)B2 + A2(x)B1   (B3 at FULL index p!)
        ob[110 + p] = a3 + Bl3[p] + a1 * Bl2[tid] + a2 * Bl1[i3];

        // level 4: A4 + B4 + A3(x)B1 + A2(x)B2 + A1(x)B3
        const float* A4  = a  + 1110 + (size_t)p * 10;
        const float* B4  = bb + 1110 + (size_t)p * 10;
        const float* B3r = Bl3 + i2 * 100 + i3 * 10;
        const float* B2r = Bl2 + i3 * 10;
        float* o4 = ob + 1110 + (size_t)p * 10;
#pragma unroll
        for (int q = 0; q < 10; ++q) {
            o4[q] = A4[q] + B4[q] + a3 * Bl1[q] + a2 * B2r[q] + a1 * B3r[q];
        }
    }
}

extern "C" void kernel_launch(void* const* d_in, const int* in_sizes, int n_in,
                              void* d_out, int out_size) {
    const float* path = (const float*)d_in[0];
    float* out = (float*)d_out;
    int B = in_sizes[0] / (SIG_L * SIG_C);
    if (B > SIG_MAXB) B = SIG_MAXB;
    sig_scan_kernel<<<B * 2, 512>>>(path);
    sig_combine_kernel<<<B * 10, 128>>>(out);
}